// round 5
// baseline (speedup 1.0000x reference)
#include <cuda_runtime.h>
#include <math.h>

// Problem dims (fixed for this dataset entry)
#define BSZ   1024
#define HDIM  512
#define VOC   512
#define G4H   2048           // 4*H
#define NCAT  2560           // 4H (gates) + V (logits) concatenated N-dim

// ---------------- static device scratch (no allocations allowed) ----------------
__device__ float g_Eproj[VOC * G4H];    // embedding @ W_ih^T + b_ih + b_hh   (4 MB)
__device__ float g_gates[BSZ * G4H];    // h_prev @ W_hh^T                    (8 MB)
__device__ float g_h[BSZ * HDIM];
__device__ float g_c[BSZ * HDIM];
__device__ float g_Wcat[NCAT * HDIM];   // [W_hh ; W_out] rows, K-contiguous  (5 MB)
__device__ int   g_tok[BSZ];

// ---------------------------------------------------------------------------
// SGEMM: C[m,n] = sum_k A[m,K]·B[n,K]  (both operands K-contiguous, "NT")
// Epilogue splits columns: n <  nsplit -> C0 (+bias0a+bias0b)
//                          n >= nsplit -> C1 (+bias1), col index n-nsplit
// nsplit is a multiple of BN so the branch is block-uniform.
// ---------------------------------------------------------------------------
template<int BM, int BN, int BK, int TM, int TN>
__global__ __launch_bounds__((BM/TM)*(BN/TN), 2)
void sgemm_nt(const float* __restrict__ A, const float* __restrict__ Bm,
              float* __restrict__ C0, int ldc0,
              const float* __restrict__ bias0a, const float* __restrict__ bias0b,
              float* __restrict__ C1, int ldc1, const float* __restrict__ bias1,
              int nsplit, int M, int N, int K)
{
    constexpr int THREADS = (BM/TM)*(BN/TN);
    constexpr int PAD = 4;
    __shared__ float As[BK][BM + PAD];
    __shared__ float Bs[BK][BN + PAD];

    const int tid  = threadIdx.x;
    const int tcol = tid % (BN/TN);
    const int trow = tid / (BN/TN);
    const int m0 = blockIdx.y * BM;
    const int n0 = blockIdx.x * BN;

    float acc[TM][TN];
#pragma unroll
    for (int i = 0; i < TM; i++)
#pragma unroll
        for (int j = 0; j < TN; j++) acc[i][j] = 0.f;

    const float* Aptr = A  + (size_t)m0 * K;
    const float* Bptr = Bm + (size_t)n0 * K;

    for (int k0 = 0; k0 < K; k0 += BK) {
        // Load A tile [BM,BK] -> As transposed (float4 global, scalar smem stores)
#pragma unroll
        for (int i = tid; i < BM*BK/4; i += THREADS) {
            int r  = i / (BK/4);
            int cv = (i % (BK/4)) * 4;
            float4 v = *reinterpret_cast<const float4*>(Aptr + (size_t)r*K + k0 + cv);
            As[cv+0][r] = v.x; As[cv+1][r] = v.y; As[cv+2][r] = v.z; As[cv+3][r] = v.w;
        }
        // Load B tile [BN,BK] -> Bs transposed
#pragma unroll
        for (int i = tid; i < BN*BK/4; i += THREADS) {
            int r  = i / (BK/4);
            int cv = (i % (BK/4)) * 4;
            float4 v = *reinterpret_cast<const float4*>(Bptr + (size_t)r*K + k0 + cv);
            Bs[cv+0][r] = v.x; Bs[cv+1][r] = v.y; Bs[cv+2][r] = v.z; Bs[cv+3][r] = v.w;
        }
        __syncthreads();

#pragma unroll
        for (int k = 0; k < BK; k++) {
            float ra[TM], rb[TN];
#pragma unroll
            for (int i = 0; i < TM; i += 4) {
                float4 v = *reinterpret_cast<const float4*>(&As[k][trow*TM + i]);
                ra[i] = v.x; ra[i+1] = v.y; ra[i+2] = v.z; ra[i+3] = v.w;
            }
#pragma unroll
            for (int j = 0; j < TN; j += 4) {
                float4 v = *reinterpret_cast<const float4*>(&Bs[k][tcol*TN + j]);
                rb[j] = v.x; rb[j+1] = v.y; rb[j+2] = v.z; rb[j+3] = v.w;
            }
#pragma unroll
            for (int i = 0; i < TM; i++)
#pragma unroll
                for (int j = 0; j < TN; j++)
                    acc[i][j] = fmaf(ra[i], rb[j], acc[i][j]);
        }
        __syncthreads();
    }

    if (n0 + BN <= nsplit) {
#pragma unroll
        for (int i = 0; i < TM; i++) {
            int m = m0 + trow*TM + i;
#pragma unroll
            for (int j = 0; j < TN; j++) {
                int n = n0 + tcol*TN + j;
                float v = acc[i][j];
                if (bias0a) v += bias0a[n];
                if (bias0b) v += bias0b[n];
                C0[(size_t)m*ldc0 + n] = v;
            }
        }
    } else {
#pragma unroll
        for (int i = 0; i < TM; i++) {
            int m = m0 + trow*TM + i;
#pragma unroll
            for (int j = 0; j < TN; j++) {
                int n = n0 + tcol*TN + j - nsplit;
                float v = acc[i][j];
                if (bias1) v += bias1[n];
                C1[(size_t)m*ldc1 + n] = v;
            }
        }
    }
}

// ---------------------------------------------------------------------------
// LSTM cell: gates = g_gates (h@W_hh^T) + Eproj[token]  (Eproj holds x@W_ih^T + biases)
// PyTorch gate order i,f,g,o. Updates g_h, g_c in place.
// ---------------------------------------------------------------------------
__global__ void lstm_cell_kernel()
{
    int idx = blockIdx.x * blockDim.x + threadIdx.x;
    if (idx >= BSZ * HDIM) return;
    int b  = idx >> 9;          // / HDIM
    int hh = idx & (HDIM - 1);

    const float* gr = g_gates + (size_t)b * G4H;
    const float* er = g_Eproj + (size_t)g_tok[b] * G4H;

    float gi = gr[hh]            + er[hh];
    float gf = gr[HDIM   + hh]   + er[HDIM   + hh];
    float gg = gr[2*HDIM + hh]   + er[2*HDIM + hh];
    float go = gr[3*HDIM + hh]   + er[3*HDIM + hh];

    float si = 1.f / (1.f + expf(-gi));
    float sf = 1.f / (1.f + expf(-gf));
    float so = 1.f / (1.f + expf(-go));
    float tg = tanhf(gg);

    float cn = sf * g_c[idx] + si * tg;
    float hn = so * tanhf(cn);
    g_c[idx] = cn;
    g_h[idx] = hn;
}

// ---------------------------------------------------------------------------
// Row argmax over V=512 logits, first-index tie-break (matches jnp.argmax).
// One warp per row; 8 warps per block.
// ---------------------------------------------------------------------------
__global__ void argmax_kernel(const float* __restrict__ logits)
{
    int row  = blockIdx.x * (blockDim.x >> 5) + (threadIdx.x >> 5);
    int lane = threadIdx.x & 31;
    if (row >= BSZ) return;

    const float* p = logits + (size_t)row * VOC;
    float best = -INFINITY;
    int   bi   = 0;
    for (int j = lane; j < VOC; j += 32) {
        float v = p[j];
        if (v > best) { best = v; bi = j; }   // ascending scan keeps first max
    }
#pragma unroll
    for (int off = 16; off; off >>= 1) {
        float ov = __shfl_xor_sync(0xffffffffu, best, off);
        int   oi = __shfl_xor_sync(0xffffffffu, bi,   off);
        if (ov > best || (ov == best && oi < bi)) { best = ov; bi = oi; }
    }
    if (lane == 0) g_tok[row] = bi;
}

// ---------------------------------------------------------------------------
extern "C" void kernel_launch(void* const* d_in, const int* in_sizes, int n_in,
                              void* d_out, int out_size)
{
    // Identify inputs by element count (dict order within equal sizes):
    // target_var(65536,i64), target_max_len(1), encoder_hidden(524288),
    // encoder_cell(524288), embedding(262144), W_ih(1048576), W_hh(1048576),
    // b_ih(2048), b_hh(2048), W_out(262144), b_out(512)
    const float *enc_h = nullptr, *enc_c = nullptr, *emb = nullptr,
                *W_ih = nullptr, *W_hh = nullptr, *b_ih = nullptr,
                *b_hh = nullptr, *W_out = nullptr, *b_out = nullptr;
    for (int i = 0; i < n_in; i++) {
        int s = in_sizes[i];
        const float* p = (const float*)d_in[i];
        if      (s == BSZ * HDIM) { if (!enc_h) enc_h = p; else if (!enc_c) enc_c = p; }
        else if (s == G4H * HDIM) { if (!W_ih)  W_ih  = p; else if (!W_hh)  W_hh  = p; }
        else if (s == VOC * HDIM) { if (!emb)   emb   = p; else if (!W_out) W_out = p; }
        else if (s == G4H)        { if (!b_ih)  b_ih  = p; else if (!b_hh)  b_hh  = p; }
        else if (s == VOC)        { if (!b_out) b_out = p; }
    }
    float* out = (float*)d_out;
    int T = out_size / (BSZ * VOC);   // 64

    float *pE, *pG, *pH, *pC, *pW; int* pT;
    cudaGetSymbolAddress((void**)&pE, g_Eproj);
    cudaGetSymbolAddress((void**)&pG, g_gates);
    cudaGetSymbolAddress((void**)&pH, g_h);
    cudaGetSymbolAddress((void**)&pC, g_c);
    cudaGetSymbolAddress((void**)&pW, g_Wcat);
    cudaGetSymbolAddress((void**)&pT, g_tok);

    // State init + weight concat (all async, graph-capturable)
    cudaMemcpyAsync(pH, enc_h, (size_t)BSZ*HDIM*4, cudaMemcpyDeviceToDevice, 0);
    cudaMemcpyAsync(pC, enc_c, (size_t)BSZ*HDIM*4, cudaMemcpyDeviceToDevice, 0);
    cudaMemcpyAsync(pW,                  W_hh,  (size_t)G4H*HDIM*4, cudaMemcpyDeviceToDevice, 0);
    cudaMemcpyAsync(pW + (size_t)G4H*HDIM, W_out, (size_t)VOC*HDIM*4, cudaMemcpyDeviceToDevice, 0);
    cudaMemsetAsync(pT, 0, BSZ * sizeof(int), 0);   // token = SOS_INDEX = 0

    // Eproj = embedding @ W_ih^T + (b_ih + b_hh)     [512 x 2048]
    sgemm_nt<128,128,16,8,8><<<dim3(G4H/128, VOC/128), 256>>>(
        emb, W_ih, pE, G4H, b_ih, b_hh,
        nullptr, 0, nullptr, /*nsplit=*/G4H, VOC, G4H, HDIM);

    // hh_part(0) = h_init @ W_hh^T                   [1024 x 2048]
    sgemm_nt<128,128,16,8,8><<<dim3(G4H/128, BSZ/128), 256>>>(
        pH, pW, pG, G4H, nullptr, nullptr,
        nullptr, 0, nullptr, /*nsplit=*/G4H, BSZ, G4H, HDIM);

    for (int t = 0; t < T; t++) {
        // cell(t): gates = g_gates + Eproj[token(t-1)] -> h(t), c(t)
        lstm_cell_kernel<<<(BSZ*HDIM + 255)/256, 256>>>();

        if (t < T - 1) {
            // Fused: [hh_part(t+1) | logits(t)] = h(t) @ [W_hh ; W_out]^T
            sgemm_nt<128,128,16,8,8><<<dim3(NCAT/128, BSZ/128), 256>>>(
                pH, pW, pG, G4H, nullptr, nullptr,
                out + (size_t)t * BSZ * VOC, VOC, b_out,
                /*nsplit=*/G4H, BSZ, NCAT, HDIM);
            // token(t) = argmax logits(t)
            argmax_kernel<<<BSZ/8, 256>>>(out + (size_t)t * BSZ * VOC);
        } else {
            // Final step: logits only
            sgemm_nt<128,64,16,8,4><<<dim3(VOC/64, BSZ/128), 256>>>(
                pH, pW + (size_t)G4H*HDIM,
                out + (size_t)t * BSZ * VOC, VOC, b_out, nullptr,
                nullptr, 0, nullptr, /*nsplit=*/VOC, BSZ, VOC, HDIM);
        }
    }
}

// round 10
// speedup vs baseline: 1.1218x; 1.1218x over previous
#include <cuda_runtime.h>
#include <math.h>

// Problem dims (fixed for this dataset entry)
#define BSZ   1024
#define HDIM  512
#define VOC   512
#define G4H   2048           // 4*H
#define NCAT  2560           // 4H (gates) + V (logits)
#define KDIM  512

// ---------------- static device scratch ----------------
__device__ float g_Eproj[VOC * G4H];    // embedding @ W_ih^T + b_ih + b_hh
__device__ float g_gates[BSZ * G4H];    // h_prev @ W_hh^T
__device__ float g_h[BSZ * HDIM];
__device__ float g_c[BSZ * HDIM];
__device__ float g_Wcat[NCAT * HDIM];   // [W_hh ; W_out], K-contiguous rows
__device__ int   g_tok[BSZ];

// ---------------- tf32 helpers (baseline sm_80+ PTX, no 'a' features) ----------------
__device__ __forceinline__ unsigned f2tf32(float x) {
    unsigned r; asm("cvt.rna.tf32.f32 %0, %1;" : "=r"(r) : "f"(x)); return r;
}
__device__ __forceinline__ void split4(float4 v, float4& h, float4& l) {
    h.x = __uint_as_float(f2tf32(v.x)); l.x = __uint_as_float(f2tf32(v.x - h.x));
    h.y = __uint_as_float(f2tf32(v.y)); l.y = __uint_as_float(f2tf32(v.y - h.y));
    h.z = __uint_as_float(f2tf32(v.z)); l.z = __uint_as_float(f2tf32(v.z - h.z));
    h.w = __uint_as_float(f2tf32(v.w)); l.w = __uint_as_float(f2tf32(v.w - h.w));
}
__device__ __forceinline__ void mma8(float* c,
                                     const unsigned* a, const unsigned* b) {
    asm volatile("mma.sync.aligned.m16n8k8.row.col.f32.tf32.tf32.f32 "
                 "{%0,%1,%2,%3}, {%4,%5,%6,%7}, {%8,%9}, {%0,%1,%2,%3};"
                 : "+f"(c[0]), "+f"(c[1]), "+f"(c[2]), "+f"(c[3])
                 : "r"(a[0]), "r"(a[1]), "r"(a[2]), "r"(a[3]), "r"(b[0]), "r"(b[1]));
}

// ---------------------------------------------------------------------------
// TF32x3 HMMA GEMM: C[m,n] = sum_k A[m,k]*B[n,k]  (NT, both K-contiguous)
// Tile 128x64, K=512 in 16 chunks of 32, double-buffered smem.
// 8 warps as 4x2; warp tile 32x32 -> 2 m-frags x 4 n-frags of m16n8k8.
// Per frag-pair: 3 mmas (AhBh + AhBl + AlBh) => fp32-faithful result.
// Epilogue split: n < nsplit -> C0 (+bias0a+bias0b) else C1 (+bias1).
// smem (floats): buf b at b*13824: Ah[128][36]=4608, Al +4608,
//                Bh[64][36]=2304 at +9216, Bl at +11520.
// ---------------------------------------------------------------------------
#define BUF_FLOATS 13824
#define AL_OFF     4608
#define BH_OFF     9216
#define BL_OFF     11520
#define MM_SMEM    (2 * BUF_FLOATS * 4)   // 110592 bytes

__global__ __launch_bounds__(256, 2)
void mm_tf32x3(const float* __restrict__ A, const float* __restrict__ Bm,
               float* __restrict__ C0, int ldc0,
               const float* __restrict__ b0a, const float* __restrict__ b0b,
               float* __restrict__ C1, int ldc1, const float* __restrict__ b1,
               int nsplit)
{
    extern __shared__ float sm[];
    const int tid  = threadIdx.x;
    const int wid  = tid >> 5, lane = tid & 31;
    const int g    = lane >> 2, t = lane & 3;
    const int m0   = blockIdx.y * 128, n0 = blockIdx.x * 64;
    const int wrow = (wid >> 1) * 32;       // warp row base in tile
    const int wcol = (wid & 1)  * 32;       // warp col base in tile

    const float* Ab = A  + (size_t)m0 * KDIM;
    const float* Bb = Bm + (size_t)n0 * KDIM;

    float c[2][4][4];
#pragma unroll
    for (int mi = 0; mi < 2; mi++)
#pragma unroll
        for (int nj = 0; nj < 4; nj++)
#pragma unroll
            for (int q = 0; q < 4; q++) c[mi][nj][q] = 0.f;

    float4 ra[4], rb[2];

    // ---- prefetch chunk 0 ----
#pragma unroll
    for (int it = 0; it < 4; it++) {
        int i = tid + it * 256;
        ra[it] = *reinterpret_cast<const float4*>(Ab + (size_t)(i >> 3) * KDIM + ((i & 7) << 2));
    }
#pragma unroll
    for (int it = 0; it < 2; it++) {
        int i = tid + it * 256;
        rb[it] = *reinterpret_cast<const float4*>(Bb + (size_t)(i >> 3) * KDIM + ((i & 7) << 2));
    }

    // store chunk 0 into buffer 0
    {
        float* base = sm;
#pragma unroll
        for (int it = 0; it < 4; it++) {
            int i = tid + it * 256, r = i >> 3, kq = (i & 7) << 2;
            float4 hv, lv; split4(ra[it], hv, lv);
            int off = r * 36 + kq;
            *reinterpret_cast<float4*>(base + off)          = hv;
            *reinterpret_cast<float4*>(base + AL_OFF + off) = lv;
        }
#pragma unroll
        for (int it = 0; it < 2; it++) {
            int i = tid + it * 256, r = i >> 3, kq = (i & 7) << 2;
            float4 hv, lv; split4(rb[it], hv, lv);
            int off = r * 36 + kq;
            *reinterpret_cast<float4*>(base + BH_OFF + off) = hv;
            *reinterpret_cast<float4*>(base + BL_OFF + off) = lv;
        }
    }
    __syncthreads();

    for (int ch = 0; ch < 16; ch++) {
        int b = ch & 1;
        // prefetch next chunk into registers (overlaps compute)
        if (ch < 15) {
            int k0g = (ch + 1) * 32;
#pragma unroll
            for (int it = 0; it < 4; it++) {
                int i = tid + it * 256;
                ra[it] = *reinterpret_cast<const float4*>(Ab + (size_t)(i >> 3) * KDIM + k0g + ((i & 7) << 2));
            }
#pragma unroll
            for (int it = 0; it < 2; it++) {
                int i = tid + it * 256;
                rb[it] = *reinterpret_cast<const float4*>(Bb + (size_t)(i >> 3) * KDIM + k0g + ((i & 7) << 2));
            }
        }

        // ---- compute chunk from buffer b ----
        const float* pAh = sm + b * BUF_FLOATS;
        const float* pAl = pAh + AL_OFF;
        const float* pBh = pAh + BH_OFF;
        const float* pBl = pAh + BL_OFF;
#pragma unroll
        for (int k8 = 0; k8 < 4; k8++) {
            int k0 = k8 * 8;
            unsigned ah[2][4], al[2][4], bh[4][2], bl[4][2];
#pragma unroll
            for (int mi = 0; mi < 2; mi++) {
                int ia = (wrow + 16 * mi + g) * 36 + k0 + t;
                ah[mi][0] = __float_as_uint(pAh[ia]);
                ah[mi][1] = __float_as_uint(pAh[ia + 8 * 36]);
                ah[mi][2] = __float_as_uint(pAh[ia + 4]);
                ah[mi][3] = __float_as_uint(pAh[ia + 8 * 36 + 4]);
                al[mi][0] = __float_as_uint(pAl[ia]);
                al[mi][1] = __float_as_uint(pAl[ia + 8 * 36]);
                al[mi][2] = __float_as_uint(pAl[ia + 4]);
                al[mi][3] = __float_as_uint(pAl[ia + 8 * 36 + 4]);
            }
#pragma unroll
            for (int nj = 0; nj < 4; nj++) {
                int ib = (wcol + 8 * nj + g) * 36 + k0 + t;
                bh[nj][0] = __float_as_uint(pBh[ib]);
                bh[nj][1] = __float_as_uint(pBh[ib + 4]);
                bl[nj][0] = __float_as_uint(pBl[ib]);
                bl[nj][1] = __float_as_uint(pBl[ib + 4]);
            }
#pragma unroll
            for (int mi = 0; mi < 2; mi++)
#pragma unroll
                for (int nj = 0; nj < 4; nj++) {
                    mma8(c[mi][nj], ah[mi], bh[nj]);   // hi*hi
                    mma8(c[mi][nj], ah[mi], bl[nj]);   // hi*lo
                    mma8(c[mi][nj], al[mi], bh[nj]);   // lo*hi
                }
        }

        // ---- store prefetched chunk into the other buffer ----
        if (ch < 15) {
            float* base = sm + (b ^ 1) * BUF_FLOATS;
#pragma unroll
            for (int it = 0; it < 4; it++) {
                int i = tid + it * 256, r = i >> 3, kq = (i & 7) << 2;
                float4 hv, lv; split4(ra[it], hv, lv);
                int off = r * 36 + kq;
                *reinterpret_cast<float4*>(base + off)          = hv;
                *reinterpret_cast<float4*>(base + AL_OFF + off) = lv;
            }
#pragma unroll
            for (int it = 0; it < 2; it++) {
                int i = tid + it * 256, r = i >> 3, kq = (i & 7) << 2;
                float4 hv, lv; split4(rb[it], hv, lv);
                int off = r * 36 + kq;
                *reinterpret_cast<float4*>(base + BH_OFF + off) = hv;
                *reinterpret_cast<float4*>(base + BL_OFF + off) = lv;
            }
            __syncthreads();
        }
    }

    // ---- epilogue: stage C in smem (stride 68), then coalesced stores ----
    // Stage area = sm[0 .. 8703] (inside buffer 0's A region; compute(15) read buffer 1).
    float* Cs = sm;
#pragma unroll
    for (int mi = 0; mi < 2; mi++)
#pragma unroll
        for (int nj = 0; nj < 4; nj++) {
            int row = wrow + 16 * mi + g;
            int col = wcol + 8 * nj + 2 * t;
            *reinterpret_cast<float2*>(&Cs[row * 68 + col]) =
                make_float2(c[mi][nj][0], c[mi][nj][1]);
            *reinterpret_cast<float2*>(&Cs[(row + 8) * 68 + col]) =
                make_float2(c[mi][nj][2], c[mi][nj][3]);
        }
    __syncthreads();

    if (n0 + 64 <= nsplit) {
        for (int i = tid; i < 128 * 16; i += 256) {
            int rr = i >> 4, cq = (i & 15) << 2;
            float4 v = *reinterpret_cast<const float4*>(&Cs[rr * 68 + cq]);
            if (b0a) { float4 x = *reinterpret_cast<const float4*>(&b0a[n0 + cq]);
                       v.x += x.x; v.y += x.y; v.z += x.z; v.w += x.w; }
            if (b0b) { float4 x = *reinterpret_cast<const float4*>(&b0b[n0 + cq]);
                       v.x += x.x; v.y += x.y; v.z += x.z; v.w += x.w; }
            *reinterpret_cast<float4*>(&C0[(size_t)(m0 + rr) * ldc0 + n0 + cq]) = v;
        }
    } else {
        int nb = n0 - nsplit;
        for (int i = tid; i < 128 * 16; i += 256) {
            int rr = i >> 4, cq = (i & 15) << 2;
            float4 v = *reinterpret_cast<const float4*>(&Cs[rr * 68 + cq]);
            float4 x = *reinterpret_cast<const float4*>(&b1[nb + cq]);
            v.x += x.x; v.y += x.y; v.z += x.z; v.w += x.w;
            *reinterpret_cast<float4*>(&C1[(size_t)(m0 + rr) * ldc1 + nb + cq]) = v;
        }
    }
}

// ---------------------------------------------------------------------------
// LSTM cell: gates = g_gates (h@W_hh^T) + Eproj[token]; PyTorch order i,f,g,o.
// ---------------------------------------------------------------------------
__global__ void lstm_cell_kernel()
{
    int idx = blockIdx.x * blockDim.x + threadIdx.x;
    if (idx >= BSZ * HDIM) return;
    int b  = idx >> 9;
    int hh = idx & (HDIM - 1);

    const float* gr = g_gates + (size_t)b * G4H;
    const float* er = g_Eproj + (size_t)g_tok[b] * G4H;

    float gi = gr[hh]          + er[hh];
    float gf = gr[HDIM + hh]   + er[HDIM + hh];
    float gg = gr[2*HDIM + hh] + er[2*HDIM + hh];
    float go = gr[3*HDIM + hh] + er[3*HDIM + hh];

    float si = 1.f / (1.f + expf(-gi));
    float sf = 1.f / (1.f + expf(-gf));
    float so = 1.f / (1.f + expf(-go));
    float tg = tanhf(gg);

    float cn = sf * g_c[idx] + si * tg;
    float hn = so * tanhf(cn);
    g_c[idx] = cn;
    g_h[idx] = hn;
}

// ---------------------------------------------------------------------------
// Row argmax over V=512, first-index tie-break (matches jnp.argmax).
// ---------------------------------------------------------------------------
__global__ void argmax_kernel(const float* __restrict__ logits)
{
    int row  = blockIdx.x * (blockDim.x >> 5) + (threadIdx.x >> 5);
    int lane = threadIdx.x & 31;
    if (row >= BSZ) return;

    const float* p = logits + (size_t)row * VOC;
    float best = -INFINITY;
    int   bi   = 0;
    for (int j = lane; j < VOC; j += 32) {
        float v = p[j];
        if (v > best) { best = v; bi = j; }
    }
#pragma unroll
    for (int off = 16; off; off >>= 1) {
        float ov = __shfl_xor_sync(0xffffffffu, best, off);
        int   oi = __shfl_xor_sync(0xffffffffu, bi,   off);
        if (ov > best || (ov == best && oi < bi)) { best = ov; bi = oi; }
    }
    if (lane == 0) g_tok[row] = bi;
}

// ---------------------------------------------------------------------------
extern "C" void kernel_launch(void* const* d_in, const int* in_sizes, int n_in,
                              void* d_out, int out_size)
{
    const float *enc_h = nullptr, *enc_c = nullptr, *emb = nullptr,
                *W_ih = nullptr, *W_hh = nullptr, *b_ih = nullptr,
                *b_hh = nullptr, *W_out = nullptr, *b_out = nullptr;
    for (int i = 0; i < n_in; i++) {
        int s = in_sizes[i];
        const float* p = (const float*)d_in[i];
        if      (s == BSZ * HDIM) { if (!enc_h) enc_h = p; else if (!enc_c) enc_c = p; }
        else if (s == G4H * HDIM) { if (!W_ih)  W_ih  = p; else if (!W_hh)  W_hh  = p; }
        else if (s == VOC * HDIM) { if (!emb)   emb   = p; else if (!W_out) W_out = p; }
        else if (s == G4H)        { if (!b_ih)  b_ih  = p; else if (!b_hh)  b_hh  = p; }
        else if (s == VOC)        { if (!b_out) b_out = p; }
    }
    float* out = (float*)d_out;
    int T = out_size / (BSZ * VOC);   // 64

    float *pE, *pG, *pH, *pC, *pW; int* pT;
    cudaGetSymbolAddress((void**)&pE, g_Eproj);
    cudaGetSymbolAddress((void**)&pG, g_gates);
    cudaGetSymbolAddress((void**)&pH, g_h);
    cudaGetSymbolAddress((void**)&pC, g_c);
    cudaGetSymbolAddress((void**)&pW, g_Wcat);
    cudaGetSymbolAddress((void**)&pT, g_tok);

    cudaFuncSetAttribute(mm_tf32x3, cudaFuncAttributeMaxDynamicSharedMemorySize, MM_SMEM);

    // State init + weight concat
    cudaMemcpyAsync(pH, enc_h, (size_t)BSZ*HDIM*4, cudaMemcpyDeviceToDevice, 0);
    cudaMemcpyAsync(pC, enc_c, (size_t)BSZ*HDIM*4, cudaMemcpyDeviceToDevice, 0);
    cudaMemcpyAsync(pW,                    W_hh,  (size_t)G4H*HDIM*4, cudaMemcpyDeviceToDevice, 0);
    cudaMemcpyAsync(pW + (size_t)G4H*HDIM, W_out, (size_t)VOC*HDIM*4, cudaMemcpyDeviceToDevice, 0);
    cudaMemsetAsync(pT, 0, BSZ * sizeof(int), 0);   // token = SOS = 0

    // Eproj = embedding @ W_ih^T + (b_ih + b_hh)   [512 x 2048]
    mm_tf32x3<<<dim3(G4H/64, VOC/128), 256, MM_SMEM>>>(
        emb, W_ih, pE, G4H, b_ih, b_hh, nullptr, 0, nullptr, G4H);

    // hh_part(0) = h_init @ W_hh^T                 [1024 x 2048]
    mm_tf32x3<<<dim3(G4H/64, BSZ/128), 256, MM_SMEM>>>(
        pH, pW, pG, G4H, nullptr, nullptr, nullptr, 0, nullptr, G4H);

    for (int t = 0; t < T; t++) {
        lstm_cell_kernel<<<(BSZ*HDIM + 255)/256, 256>>>();

        // Fused: [hh_part(t+1) | logits(t)+b_out] = h(t) @ [W_hh ; W_out]^T
        mm_tf32x3<<<dim3(NCAT/64, BSZ/128), 256, MM_SMEM>>>(
            pH, pW, pG, G4H, nullptr, nullptr,
            out + (size_t)t * BSZ * VOC, VOC, b_out, G4H);

        if (t < T - 1)
            argmax_kernel<<<BSZ/8, 256>>>(out + (size_t)t * BSZ * VOC);
    }
}

// round 11
// speedup vs baseline: 1.6723x; 1.4908x over previous
#include <cuda_runtime.h>
#include <math.h>

// Problem dims (fixed for this dataset entry)
#define BSZ   1024
#define HDIM  512
#define VOC   512
#define G4H   2048           // 4*H
#define KDIM  512

// ---------------- static device scratch ----------------
__device__ float g_Eproj[VOC * G4H];              // embedding @ W_ih^T + b_ih + b_hh
__device__ float g_gates[BSZ * G4H];              // h_prev @ W_hh^T
__device__ float g_h[BSZ * HDIM];
__device__ float g_c[BSZ * HDIM];
// Pre-split (hi,lo) tf32 weights, tile-contiguous: [n_tile][16 ch][64 rows][18 float4]
__device__ float4 g_Bpk_wih[32 * 16 * 64 * 18];   // W_ih   (2048 rows)
__device__ float4 g_Bpk_wcat[40 * 16 * 64 * 18];  // [W_hh ; W_out] (2560 rows)
__device__ unsigned long long g_amax[2][BSZ];     // per-step-parity argmax keys

// ---------------- helpers (baseline sm_80+ PTX only) ----------------
__device__ __forceinline__ unsigned f2tf32(float x) {
    unsigned r; asm("cvt.rna.tf32.f32 %0, %1;" : "=r"(r) : "f"(x)); return r;
}
__device__ __forceinline__ void split4(float4 v, float4& h, float4& l) {
    h.x = __uint_as_float(f2tf32(v.x)); l.x = __uint_as_float(f2tf32(v.x - h.x));
    h.y = __uint_as_float(f2tf32(v.y)); l.y = __uint_as_float(f2tf32(v.y - h.y));
    h.z = __uint_as_float(f2tf32(v.z)); l.z = __uint_as_float(f2tf32(v.z - h.z));
    h.w = __uint_as_float(f2tf32(v.w)); l.w = __uint_as_float(f2tf32(v.w - h.w));
}
__device__ __forceinline__ void mma8(float* c, const unsigned* a, const unsigned* b) {
    asm volatile("mma.sync.aligned.m16n8k8.row.col.f32.tf32.tf32.f32 "
                 "{%0,%1,%2,%3}, {%4,%5,%6,%7}, {%8,%9}, {%0,%1,%2,%3};"
                 : "+f"(c[0]), "+f"(c[1]), "+f"(c[2]), "+f"(c[3])
                 : "r"(a[0]), "r"(a[1]), "r"(a[2]), "r"(a[3]), "r"(b[0]), "r"(b[1]));
}
__device__ __forceinline__ unsigned smem_u32(const void* p) {
    unsigned a;
    asm("{ .reg .u64 t; cvta.to.shared.u64 t, %1; cvt.u32.u64 %0, t; }" : "=r"(a) : "l"(p));
    return a;
}
#define CP16(dst, src) asm volatile("cp.async.cg.shared.global [%0], [%1], 16;" \
                                    :: "r"(dst), "l"(src) : "memory")
#define CP_COMMIT asm volatile("cp.async.commit_group;" ::: "memory")
#define CP_WAIT0  asm volatile("cp.async.wait_group 0;" ::: "memory")
#define CP_WAIT1  asm volatile("cp.async.wait_group 1;" ::: "memory")

__device__ __forceinline__ unsigned long long amax_key(float v, int col) {
    unsigned u = __float_as_uint(v);
    unsigned m = (u & 0x80000000u) ? ~u : (u | 0x80000000u);
    return ((unsigned long long)m << 32) | (unsigned)(511 - col);
}

// ---------------------------------------------------------------------------
// Pre-split weights: rows [nrows x 512] fp32 -> (hi,lo) packed tiles.
// Layout: [tile(64 rows)][ch(16)][row(64)][18 float4]; row = 32 (hi,lo) pairs + 4 pad floats.
// ---------------------------------------------------------------------------
__global__ void prepack_B(const float* __restrict__ src, float4* __restrict__ dst, int nrows)
{
    int i = blockIdx.x * blockDim.x + threadIdx.x;   // one per k-quad
    if (i >= nrows * 128) return;
    int n = i >> 7, q = i & 127;
    float4 v = reinterpret_cast<const float4*>(src)[(size_t)n * 128 + q];
    float4 h, l; split4(v, h, l);
    int tile = n >> 6, r = n & 63, ch = q >> 3;
    int base4 = ((tile * 16 + ch) * 64 + r) * 18 + (q & 7) * 2;
    dst[base4]     = make_float4(h.x, l.x, h.y, l.y);
    dst[base4 + 1] = make_float4(h.z, l.z, h.w, l.w);
}

__global__ void init_amax()
{
    int i = blockIdx.x * blockDim.x + threadIdx.x;
    if (i < BSZ) g_amax[1][i] = (1ULL << 32) | 511ULL;   // decodes to token 0 (SOS)
}

// ---------------------------------------------------------------------------
// TF32x3 HMMA GEMM, cp.async pipelined.
// C[m,n] = sum_k A[m,k]*B[n,k]; A raw fp32 (K-contig), B pre-split packed tiles.
// Tile 128x64, K=512 in 16 chunks of 32, double-buffered smem.
// 8 warps as 4x2; warp tile 32x32. 3 mmas per frag-pair (AhBh+AhBl+AlBh).
// Epilogue: n<nsplit -> C0(+b0a+b0b); else C1(+b1) and fused row-argmax atomics.
// smem buffer b at b*13824 floats: A raw [128][36] = 4608 f, B packed [64][36 f2] = 9216 f.
// ---------------------------------------------------------------------------
#define BUF_FLOATS 13824
#define MM_SMEM    (2 * BUF_FLOATS * 4)   // 110592 bytes

__global__ __launch_bounds__(256, 2)
void mm_step(const float* __restrict__ A, const float4* __restrict__ Bpk,
             float* __restrict__ C0, int ldc0,
             const float* __restrict__ b0a, const float* __restrict__ b0b,
             float* __restrict__ C1, int ldc1, const float* __restrict__ b1,
             int nsplit, unsigned long long* __restrict__ amax)
{
    extern __shared__ float sm[];
    const unsigned sbase = smem_u32(sm);
    const int tid  = threadIdx.x;
    const int wid  = tid >> 5, lane = tid & 31;
    const int g    = lane >> 2, t = lane & 3;
    const int m0   = blockIdx.y * 128, n0 = blockIdx.x * 64;
    const int nt   = blockIdx.x;
    const int wrow = (wid >> 1) * 32;
    const int wcol = (wid & 1)  * 32;

    const float* Ab = A + (size_t)m0 * KDIM;

    // async copy of chunk ch into buffer b: A 1024 segs + B 1152 segs (16B each)
    auto cpA = [&](int ch, int b) {
        unsigned sb = sbase + b * (BUF_FLOATS * 4);
        const float*  Asrc = Ab + ch * 32;
        const float4* Bsrc = Bpk + (size_t)(nt * 16 + ch) * 1152;
#pragma unroll 1
        for (int i = tid; i < 2176; i += 256) {
            if (i < 1024) {
                int row = i >> 3, s = i & 7;
                CP16(sb + (row * 36 + s * 4) * 4, Asrc + (size_t)row * KDIM + s * 4);
            } else {
                int j = i - 1024;
                CP16(sb + 18432 + j * 16, Bsrc + j);
            }
        }
    };

    float c[2][4][4];
#pragma unroll
    for (int mi = 0; mi < 2; mi++)
#pragma unroll
        for (int nj = 0; nj < 4; nj++)
#pragma unroll
            for (int q = 0; q < 4; q++) c[mi][nj][q] = 0.f;

    cpA(0, 0); CP_COMMIT;
    cpA(1, 1); CP_COMMIT;

    for (int ch = 0; ch < 16; ch++) {
        int b = ch & 1;
        if (ch < 15) { CP_WAIT1; } else { CP_WAIT0; }
        __syncthreads();

        const float*  pA = sm + b * BUF_FLOATS;                                 // raw fp32
        const float2* pB = reinterpret_cast<const float2*>(sm + b * BUF_FLOATS + 4608); // (hi,lo)

#pragma unroll
        for (int k8 = 0; k8 < 4; k8++) {
            int k0 = k8 * 8;
            unsigned ah[2][4], al[2][4];
#pragma unroll
            for (int mi = 0; mi < 2; mi++) {
                int ia = (wrow + 16 * mi + g) * 36 + k0 + t;
                float x0 = pA[ia], x1 = pA[ia + 288], x2 = pA[ia + 4], x3 = pA[ia + 292];
                ah[mi][0] = f2tf32(x0); al[mi][0] = f2tf32(x0 - __uint_as_float(ah[mi][0]));
                ah[mi][1] = f2tf32(x1); al[mi][1] = f2tf32(x1 - __uint_as_float(ah[mi][1]));
                ah[mi][2] = f2tf32(x2); al[mi][2] = f2tf32(x2 - __uint_as_float(ah[mi][2]));
                ah[mi][3] = f2tf32(x3); al[mi][3] = f2tf32(x3 - __uint_as_float(ah[mi][3]));
            }
            unsigned bh[4][2], bl[4][2];
#pragma unroll
            for (int nj = 0; nj < 4; nj++) {
                int ib = (wcol + 8 * nj + g) * 36 + k0 + t;   // float2 units
                float2 v0 = pB[ib], v1 = pB[ib + 4];
                bh[nj][0] = __float_as_uint(v0.x); bl[nj][0] = __float_as_uint(v0.y);
                bh[nj][1] = __float_as_uint(v1.x); bl[nj][1] = __float_as_uint(v1.y);
            }
#pragma unroll
            for (int mi = 0; mi < 2; mi++)
#pragma unroll
                for (int nj = 0; nj < 4; nj++) {
                    mma8(c[mi][nj], ah[mi], bh[nj]);
                    mma8(c[mi][nj], ah[mi], bl[nj]);
                    mma8(c[mi][nj], al[mi], bh[nj]);
                }
        }

        if (ch < 14) { __syncthreads(); cpA(ch + 2, b); CP_COMMIT; }
    }

    // ---- epilogue: stage C in smem (stride 68), coalesced stores, fused argmax ----
    float* Cs = sm;   // buffer0 region is free (last compute used buffer1)
#pragma unroll
    for (int mi = 0; mi < 2; mi++)
#pragma unroll
        for (int nj = 0; nj < 4; nj++) {
            int row = wrow + 16 * mi + g;
            int col = wcol + 8 * nj + 2 * t;
            *reinterpret_cast<float2*>(&Cs[row * 68 + col]) =
                make_float2(c[mi][nj][0], c[mi][nj][1]);
            *reinterpret_cast<float2*>(&Cs[(row + 8) * 68 + col]) =
                make_float2(c[mi][nj][2], c[mi][nj][3]);
        }
    __syncthreads();

    if (n0 + 64 <= nsplit) {
        for (int i = tid; i < 128 * 16; i += 256) {
            int rr = i >> 4, cq = (i & 15) << 2;
            float4 v = *reinterpret_cast<const float4*>(&Cs[rr * 68 + cq]);
            if (b0a) { float4 x = *reinterpret_cast<const float4*>(&b0a[n0 + cq]);
                       v.x += x.x; v.y += x.y; v.z += x.z; v.w += x.w; }
            if (b0b) { float4 x = *reinterpret_cast<const float4*>(&b0b[n0 + cq]);
                       v.x += x.x; v.y += x.y; v.z += x.z; v.w += x.w; }
            *reinterpret_cast<float4*>(&C0[(size_t)(m0 + rr) * ldc0 + n0 + cq]) = v;
        }
    } else {
        int nb = n0 - nsplit;
        for (int i = tid; i < 128 * 16; i += 256) {
            int rr = i >> 4, cq = (i & 15) << 2;
            float4 v = *reinterpret_cast<const float4*>(&Cs[rr * 68 + cq]);
            float4 x = *reinterpret_cast<const float4*>(&b1[nb + cq]);
            v.x += x.x; v.y += x.y; v.z += x.z; v.w += x.w;
            *reinterpret_cast<float4*>(&C1[(size_t)(m0 + rr) * ldc1 + nb + cq]) = v;

            // fused argmax partial: max over this thread's 4 cols, then 16-lane reduce
            int col = nb + cq;
            unsigned long long k = amax_key(v.x, col);
            unsigned long long k2 = amax_key(v.y, col + 1); if (k2 > k) k = k2;
            k2 = amax_key(v.z, col + 2); if (k2 > k) k = k2;
            k2 = amax_key(v.w, col + 3); if (k2 > k) k = k2;
#pragma unroll
            for (int off = 8; off; off >>= 1) {
                unsigned long long o = __shfl_down_sync(0xffffffffu, k, off, 16);
                if (o > k) k = o;
            }
            if ((tid & 15) == 0) atomicMax(&amax[m0 + rr], k);
        }
    }
}

// ---------------------------------------------------------------------------
// LSTM cell: gates = g_gates (h@W_hh^T) + Eproj[token]; PyTorch order i,f,g,o.
// Reads token from g_amax[par^1]; resets g_amax[par] for this step's GEMM.
// ---------------------------------------------------------------------------
__global__ void lstm_cell_kernel(int par)
{
    int idx = blockIdx.x * blockDim.x + threadIdx.x;
    if (idx >= BSZ * HDIM) return;
    int b  = idx >> 9;
    int hh = idx & (HDIM - 1);

    unsigned tok = 511u - (unsigned)(g_amax[par ^ 1][b] & 0xFFFFFFFFull);
    if (hh == 0) g_amax[par][b] = 0ull;

    const float* gr = g_gates + (size_t)b * G4H;
    const float* er = g_Eproj + (size_t)tok * G4H;

    float gi = gr[hh]          + er[hh];
    float gf = gr[HDIM + hh]   + er[HDIM + hh];
    float gg = gr[2*HDIM + hh] + er[2*HDIM + hh];
    float go = gr[3*HDIM + hh] + er[3*HDIM + hh];

    float si = 1.f / (1.f + expf(-gi));
    float sf = 1.f / (1.f + expf(-gf));
    float so = 1.f / (1.f + expf(-go));
    float tg = tanhf(gg);

    float cn = sf * g_c[idx] + si * tg;
    float hn = so * tanhf(cn);
    g_c[idx] = cn;
    g_h[idx] = hn;
}

// ---------------------------------------------------------------------------
extern "C" void kernel_launch(void* const* d_in, const int* in_sizes, int n_in,
                              void* d_out, int out_size)
{
    const float *enc_h = nullptr, *enc_c = nullptr, *emb = nullptr,
                *W_ih = nullptr, *W_hh = nullptr, *b_ih = nullptr,
                *b_hh = nullptr, *W_out = nullptr, *b_out = nullptr;
    for (int i = 0; i < n_in; i++) {
        int s = in_sizes[i];
        const float* p = (const float*)d_in[i];
        if      (s == BSZ * HDIM) { if (!enc_h) enc_h = p; else if (!enc_c) enc_c = p; }
        else if (s == G4H * HDIM) { if (!W_ih)  W_ih  = p; else if (!W_hh)  W_hh  = p; }
        else if (s == VOC * HDIM) { if (!emb)   emb   = p; else if (!W_out) W_out = p; }
        else if (s == G4H)        { if (!b_ih)  b_ih  = p; else if (!b_hh)  b_hh  = p; }
        else if (s == VOC)        { if (!b_out) b_out = p; }
    }
    float* out = (float*)d_out;
    int T = out_size / (BSZ * VOC);   // 64

    float *pE, *pG, *pH, *pC; float4 *pBwih, *pBwcat; unsigned long long* pAmax;
    cudaGetSymbolAddress((void**)&pE, g_Eproj);
    cudaGetSymbolAddress((void**)&pG, g_gates);
    cudaGetSymbolAddress((void**)&pH, g_h);
    cudaGetSymbolAddress((void**)&pC, g_c);
    cudaGetSymbolAddress((void**)&pBwih, g_Bpk_wih);
    cudaGetSymbolAddress((void**)&pBwcat, g_Bpk_wcat);
    cudaGetSymbolAddress((void**)&pAmax, g_amax);

    cudaFuncSetAttribute(mm_step, cudaFuncAttributeMaxDynamicSharedMemorySize, MM_SMEM);

    // Prologue: state init + weight pre-split + amax init
    cudaMemcpyAsync(pC, enc_c, (size_t)BSZ*HDIM*4, cudaMemcpyDeviceToDevice, 0);
    prepack_B<<<(2048*128)/256, 256>>>(W_ih,  pBwih, 2048);
    prepack_B<<<(2048*128)/256, 256>>>(W_hh,  pBwcat, 2048);
    prepack_B<<<(512*128)/256,  256>>>(W_out, pBwcat + 32*16*64*18, 512);
    init_amax<<<4, 256>>>();

    // Eproj = embedding @ W_ih^T + (b_ih + b_hh)   [512 x 2048]
    mm_step<<<dim3(32, 4), 256, MM_SMEM>>>(
        emb, pBwih, pE, G4H, b_ih, b_hh, nullptr, 0, nullptr, G4H, nullptr);

    // hh_part(0) = enc_h @ W_hh^T                  [1024 x 2048]
    mm_step<<<dim3(32, 8), 256, MM_SMEM>>>(
        enc_h, pBwcat, pG, G4H, nullptr, nullptr, nullptr, 0, nullptr, G4H, nullptr);

    for (int t = 0; t < T; t++) {
        lstm_cell_kernel<<<(BSZ*HDIM + 255)/256, 256>>>(t & 1);

        // Fused: [hh_part(t+1) | logits(t)+b_out] = h(t) @ [W_hh ; W_out]^T
        // Logits tiles also feed fused argmax atomics into g_amax[t&1].
        mm_step<<<dim3(40, 8), 256, MM_SMEM>>>(
            pH, pBwcat, pG, G4H, nullptr, nullptr,
            out + (size_t)t * BSZ * VOC, VOC, b_out, G4H,
            pAmax + (size_t)(t & 1) * BSZ);
    }
}